// round 11
// baseline (speedup 1.0000x reference)
#include <cuda_runtime.h>
#include <math.h>

// Problem dims (fixed by the dataset)
#define N_B 256
#define T_S 128
#define I_D 512
#define H_D 512
#define G4  2048            // 4*H
#define NT  32768           // N_B*T_S

typedef unsigned long long ull;

// ---------------- scratch (static device memory; no runtime allocs) --------
__device__ float g_xw[(size_t)NT * G4];     // x@W_ih^T + bias, gate-permuted
__device__ float g_hs[(size_t)NT * H_D];    // all h_t, row = n*T+t
__device__ float g_hT[2][(size_t)H_D * N_B];// ping-pong hidden state, [k][n]
__device__ float g_cT[(size_t)H_D * N_B];   // initial cell state, [k][n]
__device__ float g_rT[T_S * N_B];           // reset mask, [t][n]
__device__ float g_hfin[(size_t)N_B * H_D]; // final h, [n][k] (for bcast)
__device__ float g_cfin[(size_t)N_B * H_D]; // final c, [n][k]
__device__ float g_Wih_t[I_D * G4];         // W_ih^T, gate-permuted cols
__device__ float g_Whh_t[H_D * G4];         // W_hh^T, gate-permuted cols
__device__ float g_Wout_t[H_D * H_D];       // W_out^T
__device__ float g_bias[G4];                // (b_ih+b_hh), gate-permuted
__device__ unsigned g_bar4[4];              // per-n-group barrier counters

// ---------------- packed f32x2 helpers --------------------------------------
__device__ __forceinline__ ull pack2(float x, float y) {
    ull r;
    asm("mov.b64 %0, {%1, %2};" : "=l"(r) : "f"(x), "f"(y));
    return r;
}
__device__ __forceinline__ ull dup2(float v) {
    ull r;
    asm("mov.b64 %0, {%1, %1};" : "=l"(r) : "f"(v));
    return r;
}
__device__ __forceinline__ void fma2u(ull &d, ull a, ull b) {
    asm("fma.rn.f32x2 %0, %1, %2, %0;" : "+l"(d) : "l"(a), "l"(b));
}
__device__ __forceinline__ float2 unpack2(ull v) {
    float2 r;
    asm("mov.b64 {%0, %1}, %2;" : "=f"(r.x), "=f"(r.y) : "l"(v));
    return r;
}

__device__ __forceinline__ float sigf(float x) { return 1.0f / (1.0f + expf(-x)); }

// ---------------- weight prep: transpose + gate-quadruple permutation ------
// permuted column p = 4*jh + g  <->  original gate row orig = g*H + jh
__global__ void prep_kernel(const float* __restrict__ W_ih,
                            const float* __restrict__ W_hh,
                            const float* __restrict__ b_ih,
                            const float* __restrict__ b_hh,
                            const float* __restrict__ W_out) {
    int i = blockIdx.x * blockDim.x + threadIdx.x;
    if (i < I_D * G4) {
        int k = i / G4, p = i % G4;
        int orig = (p & 3) * H_D + (p >> 2);
        g_Wih_t[i] = W_ih[(size_t)orig * I_D + k];
        g_Whh_t[i] = W_hh[(size_t)orig * H_D + k];
    }
    if (i < H_D * H_D) {
        int k = i / H_D, j = i % H_D;
        g_Wout_t[i] = W_out[(size_t)j * H_D + k];
    }
    if (i < G4) {
        int orig = (i & 3) * H_D + (i >> 2);
        g_bias[i] = b_ih[orig] + b_hh[orig];
    }
}

// ---------------- init: transposed h0/c0, reset mask, barrier reset --------
__global__ void init_kernel(const float* __restrict__ hx,
                            const float* __restrict__ cx,
                            const int* __restrict__ is_init) {
    int i = blockIdx.x * blockDim.x + threadIdx.x;
    if (i < 4) g_bar4[i] = 0u;
    if (i < N_B * H_D) {
        int n = i >> 9, k = i & 511;
        g_hT[0][(size_t)k * N_B + n] = hx[(size_t)n * T_S * H_D + k];
        g_cT[(size_t)k * N_B + n]    = cx[(size_t)n * T_S * H_D + k];
    }
    if (i < T_S * N_B) {
        int t = i >> 8, n = i & 255;
        g_rT[i] = 1.0f - (float)is_init[n * T_S + t];
    }
}

// ---------------- pre-GEMM: g_xw = x @ Wih_t + bias (permuted cols) --------
// (exact 4559us version: 128x128 tile, BK=16, 256 threads, 8x8 via f32x2)
__global__ __launch_bounds__(256) void gemm_xw_kernel(const float* __restrict__ x) {
    __shared__ float As[16][128];
    __shared__ float Bs[16][128];
    int tid = threadIdx.x;
    int m0 = blockIdx.y * 128;
    int n0 = blockIdx.x * 128;
    int ty = tid >> 4, tx = tid & 15;

    int arow = tid >> 2;
    int akq  = (tid & 3) * 4;
    int brow = tid >> 5;
    int bcol = (tid & 31) * 4;

    ull acc[8][4] = {};

    for (int k0 = 0; k0 < I_D; k0 += 16) {
        float4 a0 = *(const float4*)(x + (size_t)(m0 + arow)      * I_D + k0 + akq);
        float4 a1 = *(const float4*)(x + (size_t)(m0 + arow + 64) * I_D + k0 + akq);
        float4 b0 = *(const float4*)(g_Wih_t + (size_t)(k0 + brow)     * G4 + n0 + bcol);
        float4 b1 = *(const float4*)(g_Wih_t + (size_t)(k0 + brow + 8) * G4 + n0 + bcol);
        __syncthreads();
        As[akq + 0][arow] = a0.x; As[akq + 1][arow] = a0.y;
        As[akq + 2][arow] = a0.z; As[akq + 3][arow] = a0.w;
        As[akq + 0][arow + 64] = a1.x; As[akq + 1][arow + 64] = a1.y;
        As[akq + 2][arow + 64] = a1.z; As[akq + 3][arow + 64] = a1.w;
        *(float4*)&Bs[brow][bcol]     = b0;
        *(float4*)&Bs[brow + 8][bcol] = b1;
        __syncthreads();
#pragma unroll
        for (int kk = 0; kk < 16; kk++) {
            float4 aA = *(float4*)&As[kk][ty * 8];
            float4 aB = *(float4*)&As[kk][ty * 8 + 4];
            float4 bA = *(float4*)&Bs[kk][tx * 8];
            float4 bB = *(float4*)&Bs[kk][tx * 8 + 4];
            ull bp0 = pack2(bA.x, bA.y);
            ull bp1 = pack2(bA.z, bA.w);
            ull bp2 = pack2(bB.x, bB.y);
            ull bp3 = pack2(bB.z, bB.w);
            float av[8] = {aA.x, aA.y, aA.z, aA.w, aB.x, aB.y, aB.z, aB.w};
#pragma unroll
            for (int i = 0; i < 8; i++) {
                ull ap = dup2(av[i]);
                fma2u(acc[i][0], ap, bp0);
                fma2u(acc[i][1], ap, bp1);
                fma2u(acc[i][2], ap, bp2);
                fma2u(acc[i][3], ap, bp3);
            }
        }
    }
#pragma unroll
    for (int i = 0; i < 8; i++) {
        int m = m0 + ty * 8 + i;
#pragma unroll
        for (int j = 0; j < 4; j++) {
            float2 v = unpack2(acc[i][j]);
            int c = n0 + tx * 8 + j * 2;
            v.x += g_bias[c];
            v.y += g_bias[c + 1];
            *(float2*)&g_xw[(size_t)m * G4 + c] = v;
        }
    }
}

// ---------------- persistent recurrence: all 128 timesteps in one kernel ---
// grid (32,4), 256 threads. CTA tile: 64 batch (n) x 64 gate-cols (16 units).
// Thread map: tn=tid&15 -> 4 n (A distinct per lane), tc=tid>>4 -> 1 hidden
// unit / 4 gate cols (B warp-broadcast). W_hh slice resident in SMEM (128KB).
// A staged in 32-k double buffers (16 syncs/step). c lives in registers.
// Cross-CTA sync: per-n-group barrier over 32 CTAs (4 independent groups).
__global__ __launch_bounds__(256, 1) void lstm_persist_kernel() {
    extern __shared__ float smem[];
    float* Ws = smem;                   // [512][64]  128KB
    float* Ab = smem + 512 * 64;        // 2 x [32][64]  16KB

    const int tid = threadIdx.x;
    const int c0  = blockIdx.x * 64;    // gate cols (permuted)
    const int gy  = blockIdx.y;         // n group
    const int n0  = gy * 64;            // batch base

    const int tn = tid & 15;            // n quad: rows n0+tn*4 .. +3
    const int tc = tid >> 4;            // col quad: cols c0+tc*4 .. +3 (1 unit)
    const int jh = (c0 >> 2) + tc;      // hidden unit owned by this thread
    const int nb = n0 + tn * 4;

    // staging map: 2 tasks/thread: (k=sk, nq) and (k=sk+16, nq)
    const int sk  = tid >> 4;           // 0..15
    const int snq = (tid & 15) * 4;

    // ---- load W_hh slice into SMEM once: Ws[k][cl] = g_Whh_t[k*G4 + c0+cl]
    for (int i = tid; i < 512 * 16; i += 256) {
        int k = i >> 4, cl = (i & 15) * 4;
        *(float4*)&Ws[k * 64 + cl] =
            *(const float4*)(g_Whh_t + (size_t)k * G4 + c0 + cl);
    }

    // c state in registers: c for (jh, nb..nb+3)
    float4 creg = *(const float4*)&g_cT[(size_t)jh * N_B + nb];
    __syncthreads();

    float* buf0 = Ab;
    float* buf1 = Ab + 32 * 64;

    for (int t = 0; t < T_S; t++) {
        const float* hin  = g_hT[t & 1];
        float*       hout = g_hT[(t + 1) & 1];

        // ---- prefetch epilogue operands (DRAM; consumed ~9us later)
        float4 xw0, xw1, xw2, xw3;
        {
            size_t base = ((size_t)nb * T_S + t) * G4 + c0 + tc * 4;
            const size_t rstride = (size_t)T_S * G4;
            xw0 = __ldcg((const float4*)(g_xw + base));
            xw1 = __ldcg((const float4*)(g_xw + base + rstride));
            xw2 = __ldcg((const float4*)(g_xw + base + 2 * rstride));
            xw3 = __ldcg((const float4*)(g_xw + base + 3 * rstride));
        }
        const float4 rr4 = *(const float4*)&g_rT[t * N_B + nb];
        const float4 r4s = *(const float4*)&g_rT[t * N_B + n0 + snq];

        // ---- stage k-block 0 (ld.cg: h ping-pong must bypass L1)
        {
            float4 h0 = __ldcg((const float4*)(hin + (size_t)sk        * N_B + n0 + snq));
            float4 h1 = __ldcg((const float4*)(hin + (size_t)(sk + 16) * N_B + n0 + snq));
            *(float4*)&buf0[sk        * 64 + snq] =
                make_float4(h0.x * r4s.x, h0.y * r4s.y, h0.z * r4s.z, h0.w * r4s.w);
            *(float4*)&buf0[(sk + 16) * 64 + snq] =
                make_float4(h1.x * r4s.x, h1.y * r4s.y, h1.z * r4s.z, h1.w * r4s.w);
        }
        __syncthreads();

        ull acc[4][2] = {};
        float* cur = buf0;
        float* nxt = buf1;

        for (int kb = 0; kb < 512; kb += 32) {
            float4 p0, p1;
            if (kb < 480) {
                p0 = __ldcg((const float4*)(hin + (size_t)(kb + 32 + sk)      * N_B + n0 + snq));
                p1 = __ldcg((const float4*)(hin + (size_t)(kb + 32 + sk + 16) * N_B + n0 + snq));
            }

            const float* Wk = Ws + kb * 64;
#pragma unroll
            for (int kk = 0; kk < 32; kk++) {
                float4 av = *(const float4*)(cur + kk * 64 + tn * 4);
                float4 bv = *(const float4*)(Wk + kk * 64 + tc * 4);
                ull bp0 = pack2(bv.x, bv.y);
                ull bp1 = pack2(bv.z, bv.w);
                float aa[4] = {av.x, av.y, av.z, av.w};
#pragma unroll
                for (int i = 0; i < 4; i++) {
                    ull ap = dup2(aa[i]);
                    fma2u(acc[i][0], ap, bp0);
                    fma2u(acc[i][1], ap, bp1);
                }
            }

            if (kb < 480) {
                *(float4*)&nxt[sk        * 64 + snq] =
                    make_float4(p0.x * r4s.x, p0.y * r4s.y, p0.z * r4s.z, p0.w * r4s.w);
                *(float4*)&nxt[(sk + 16) * 64 + snq] =
                    make_float4(p1.x * r4s.x, p1.y * r4s.y, p1.z * r4s.z, p1.w * r4s.w);
            }
            __syncthreads();
            float* tmp = cur; cur = nxt; nxt = tmp;
        }

        // ---- fused LSTM cell epilogue: 4 cells (4 n, 1 hidden unit)
        float hv[4];
        {
            const float4 xws[4] = {xw0, xw1, xw2, xw3};
            const float  rrs[4] = {rr4.x, rr4.y, rr4.z, rr4.w};
            float* cp = (float*)&creg;
#pragma unroll
            for (int i = 0; i < 4; i++) {
                float2 gif = unpack2(acc[i][0]);
                float2 ggo = unpack2(acc[i][1]);
                float gi = gif.x + xws[i].x;
                float gf = gif.y + xws[i].y;
                float gg = ggo.x + xws[i].z;
                float go = ggo.y + xws[i].w;
                float cn = sigf(gf) * (cp[i] * rrs[i]) + sigf(gi) * tanhf(gg);
                float hn = sigf(go) * tanhf(cn);
                cp[i] = cn;
                hv[i] = hn;
                g_hs[((size_t)(nb + i) * T_S + t) * H_D + jh] = hn;
            }
        }
        *(float4*)&hout[(size_t)jh * N_B + nb] = make_float4(hv[0], hv[1], hv[2], hv[3]);

        if (t == T_S - 1) {
#pragma unroll
            for (int i = 0; i < 4; i++) {
                g_hfin[(size_t)(nb + i) * H_D + jh] = hv[i];
                g_cfin[(size_t)(nb + i) * H_D + jh] = ((float*)&creg)[i];
            }
        }

        // ---- per-group grid barrier (32 CTAs sharing this n-slice)
        if (t < T_S - 1) {
            __syncthreads();
            if (tid == 0) {
                __threadfence();
                atomicAdd(&g_bar4[gy], 1u);
                unsigned target = 32u * (unsigned)(t + 1);
                while (*(volatile unsigned*)&g_bar4[gy] < target) { }
                __threadfence();
            }
            __syncthreads();
        }
    }
}

// ---------------- output GEMM: out = mish(hs @ Wout_t + b_out) -------------
__global__ __launch_bounds__(256) void gemm_out_kernel(const float* __restrict__ b_out,
                                                       float* __restrict__ out) {
    __shared__ float As[16][128];
    __shared__ float Bs[16][128];
    int tid = threadIdx.x;
    int m0 = blockIdx.y * 128;
    int n0 = blockIdx.x * 128;
    int ty = tid >> 4, tx = tid & 15;

    int arow = tid >> 2;
    int akq  = (tid & 3) * 4;
    int brow = tid >> 5;
    int bcol = (tid & 31) * 4;

    ull acc[8][4] = {};

    for (int k0 = 0; k0 < H_D; k0 += 16) {
        float4 a0 = *(const float4*)(g_hs + (size_t)(m0 + arow)      * H_D + k0 + akq);
        float4 a1 = *(const float4*)(g_hs + (size_t)(m0 + arow + 64) * H_D + k0 + akq);
        float4 b0 = *(const float4*)(g_Wout_t + (size_t)(k0 + brow)     * H_D + n0 + bcol);
        float4 b1 = *(const float4*)(g_Wout_t + (size_t)(k0 + brow + 8) * H_D + n0 + bcol);
        __syncthreads();
        As[akq + 0][arow] = a0.x; As[akq + 1][arow] = a0.y;
        As[akq + 2][arow] = a0.z; As[akq + 3][arow] = a0.w;
        As[akq + 0][arow + 64] = a1.x; As[akq + 1][arow + 64] = a1.y;
        As[akq + 2][arow + 64] = a1.z; As[akq + 3][arow + 64] = a1.w;
        *(float4*)&Bs[brow][bcol]     = b0;
        *(float4*)&Bs[brow + 8][bcol] = b1;
        __syncthreads();
#pragma unroll
        for (int kk = 0; kk < 16; kk++) {
            float4 aA = *(float4*)&As[kk][ty * 8];
            float4 aB = *(float4*)&As[kk][ty * 8 + 4];
            float4 bA = *(float4*)&Bs[kk][tx * 8];
            float4 bB = *(float4*)&Bs[kk][tx * 8 + 4];
            ull bp0 = pack2(bA.x, bA.y);
            ull bp1 = pack2(bA.z, bA.w);
            ull bp2 = pack2(bB.x, bB.y);
            ull bp3 = pack2(bB.z, bB.w);
            float av[8] = {aA.x, aA.y, aA.z, aA.w, aB.x, aB.y, aB.z, aB.w};
#pragma unroll
            for (int i = 0; i < 8; i++) {
                ull ap = dup2(av[i]);
                fma2u(acc[i][0], ap, bp0);
                fma2u(acc[i][1], ap, bp1);
                fma2u(acc[i][2], ap, bp2);
                fma2u(acc[i][3], ap, bp3);
            }
        }
    }
#pragma unroll
    for (int i = 0; i < 8; i++) {
        int m = m0 + ty * 8 + i;
#pragma unroll
        for (int j = 0; j < 4; j++) {
            float2 v = unpack2(acc[i][j]);
            int c = n0 + tx * 8 + j * 2;
            float v0 = v.x + b_out[c];
            float v1 = v.y + b_out[c + 1];
            // mish(x) = x * tanh(log1p(exp(x)))
            float o0 = v0 * tanhf(log1pf(expf(v0)));
            float o1 = v1 * tanhf(log1pf(expf(v1)));
            out[(size_t)m * H_D + c]     = o0;
            out[(size_t)m * H_D + c + 1] = o1;
        }
    }
}

// ---------------- broadcast hT, cT to [N,T,H] -------------------------------
__global__ void bcast_kernel(float* __restrict__ out) {
    int i = blockIdx.x * blockDim.x + threadIdx.x;   // over NT*H_D/4 float4s
    if (i < NT * H_D / 4) {
        int row = i >> 7;      // H_D/4 = 128 float4 per row; row = n*T+t
        int f4  = i & 127;
        int n   = row >> 7;    // T = 128
        float4 hv = *(const float4*)&g_hfin[(size_t)n * H_D + f4 * 4];
        float4 cv = *(const float4*)&g_cfin[(size_t)n * H_D + f4 * 4];
        float4* o = (float4*)out;
        o[(size_t)(NT * H_D / 4) + i]     = hv;
        o[(size_t)(NT * H_D / 4) * 2 + i] = cv;
    }
}

// ---------------- launch ----------------------------------------------------
extern "C" void kernel_launch(void* const* d_in, const int* in_sizes, int n_in,
                              void* d_out, int out_size) {
    const float* x      = (const float*)d_in[0];
    const int*   isinit = (const int*)  d_in[1];
    const float* hx     = (const float*)d_in[2];
    const float* cx     = (const float*)d_in[3];
    const float* W_ih   = (const float*)d_in[4];
    const float* W_hh   = (const float*)d_in[5];
    const float* b_ih   = (const float*)d_in[6];
    const float* b_hh   = (const float*)d_in[7];
    const float* W_out  = (const float*)d_in[8];
    const float* b_out  = (const float*)d_in[9];
    float* out = (float*)d_out;

    const int SMEM_BYTES = (512 * 64 + 2 * 32 * 64) * (int)sizeof(float);  // 147456
    cudaFuncSetAttribute(lstm_persist_kernel,
                         cudaFuncAttributeMaxDynamicSharedMemorySize, SMEM_BYTES);

    prep_kernel<<<(I_D * G4 + 255) / 256, 256>>>(W_ih, W_hh, b_ih, b_hh, W_out);
    init_kernel<<<(N_B * H_D + 255) / 256, 256>>>(hx, cx, isinit);

    { dim3 g(G4 / 128, NT / 128); gemm_xw_kernel<<<g, 256>>>(x); }

    { dim3 g(32, 4); lstm_persist_kernel<<<g, 256, SMEM_BYTES>>>(); }

    { dim3 g(H_D / 128, NT / 128); gemm_out_kernel<<<g, 256>>>(b_out, out); }

    bcast_kernel<<<(NT * H_D / 4 + 255) / 256, 256>>>(out);
}

// round 12
// speedup vs baseline: 1.0012x; 1.0012x over previous
#include <cuda_runtime.h>
#include <math.h>

// Problem dims (fixed by the dataset)
#define N_B 256
#define T_S 128
#define I_D 512
#define H_D 512
#define G4  2048            // 4*H
#define NT  32768           // N_B*T_S

typedef unsigned long long ull;

// ---------------- scratch (static device memory; no runtime allocs) --------
__device__ float g_xw[(size_t)NT * G4];     // x@W_ih^T + bias, gate-permuted
__device__ float g_hs[(size_t)NT * H_D];    // all h_t, row = n*T+t
__device__ float g_hT[2][(size_t)H_D * N_B];// ping-pong hidden state, [k][n]
__device__ float g_cT[(size_t)H_D * N_B];   // initial cell state, [k][n]
__device__ float g_rT[T_S * N_B];           // reset mask, [t][n]
__device__ float g_hfin[(size_t)N_B * H_D]; // final h, [n][k] (for bcast)
__device__ float g_cfin[(size_t)N_B * H_D]; // final c, [n][k]
__device__ float g_Wih_t[I_D * G4];         // W_ih^T, gate-permuted cols
__device__ float g_Whh_t[H_D * G4];         // W_hh^T, gate-permuted cols
__device__ float g_Wout_t[H_D * H_D];       // W_out^T
__device__ float g_bias[G4];                // (b_ih+b_hh), gate-permuted
__device__ unsigned g_bar4[4];              // per-n-group barrier counters

// ---------------- packed f32x2 helpers --------------------------------------
__device__ __forceinline__ ull pack2(float x, float y) {
    ull r;
    asm("mov.b64 %0, {%1, %2};" : "=l"(r) : "f"(x), "f"(y));
    return r;
}
__device__ __forceinline__ ull dup2(float v) {
    ull r;
    asm("mov.b64 %0, {%1, %1};" : "=l"(r) : "f"(v));
    return r;
}
__device__ __forceinline__ void fma2u(ull &d, ull a, ull b) {
    asm("fma.rn.f32x2 %0, %1, %2, %0;" : "+l"(d) : "l"(a), "l"(b));
}
__device__ __forceinline__ float2 unpack2(ull v) {
    float2 r;
    asm("mov.b64 {%0, %1}, %2;" : "=f"(r.x), "=f"(r.y) : "l"(v));
    return r;
}

__device__ __forceinline__ float sigf(float x) { return 1.0f / (1.0f + expf(-x)); }

// ---------------- weight prep: transpose + gate-quadruple permutation ------
// permuted column p = 4*jh + g  <->  original gate row orig = g*H + jh
__global__ void prep_kernel(const float* __restrict__ W_ih,
                            const float* __restrict__ W_hh,
                            const float* __restrict__ b_ih,
                            const float* __restrict__ b_hh,
                            const float* __restrict__ W_out) {
    int i = blockIdx.x * blockDim.x + threadIdx.x;
    if (i < I_D * G4) {
        int k = i / G4, p = i % G4;
        int orig = (p & 3) * H_D + (p >> 2);
        g_Wih_t[i] = W_ih[(size_t)orig * I_D + k];
        g_Whh_t[i] = W_hh[(size_t)orig * H_D + k];
    }
    if (i < H_D * H_D) {
        int k = i / H_D, j = i % H_D;
        g_Wout_t[i] = W_out[(size_t)j * H_D + k];
    }
    if (i < G4) {
        int orig = (i & 3) * H_D + (i >> 2);
        g_bias[i] = b_ih[orig] + b_hh[orig];
    }
}

// ---------------- init: transposed h0/c0, reset mask, barrier reset --------
__global__ void init_kernel(const float* __restrict__ hx,
                            const float* __restrict__ cx,
                            const int* __restrict__ is_init) {
    int i = blockIdx.x * blockDim.x + threadIdx.x;
    if (i < 4) g_bar4[i] = 0u;
    if (i < N_B * H_D) {
        int n = i >> 9, k = i & 511;
        g_hT[0][(size_t)k * N_B + n] = hx[(size_t)n * T_S * H_D + k];
        g_cT[(size_t)k * N_B + n]    = cx[(size_t)n * T_S * H_D + k];
    }
    if (i < T_S * N_B) {
        int t = i >> 8, n = i & 255;
        g_rT[i] = 1.0f - (float)is_init[n * T_S + t];
    }
}

// ---------------- pre-GEMM: g_xw = x @ Wih_t + bias (permuted cols) --------
// (exact 4559us version: 128x128 tile, BK=16, 256 threads, 8x8 via f32x2)
__global__ __launch_bounds__(256) void gemm_xw_kernel(const float* __restrict__ x) {
    __shared__ float As[16][128];
    __shared__ float Bs[16][128];
    int tid = threadIdx.x;
    int m0 = blockIdx.y * 128;
    int n0 = blockIdx.x * 128;
    int ty = tid >> 4, tx = tid & 15;

    int arow = tid >> 2;
    int akq  = (tid & 3) * 4;
    int brow = tid >> 5;
    int bcol = (tid & 31) * 4;

    ull acc[8][4] = {};

    for (int k0 = 0; k0 < I_D; k0 += 16) {
        float4 a0 = *(const float4*)(x + (size_t)(m0 + arow)      * I_D + k0 + akq);
        float4 a1 = *(const float4*)(x + (size_t)(m0 + arow + 64) * I_D + k0 + akq);
        float4 b0 = *(const float4*)(g_Wih_t + (size_t)(k0 + brow)     * G4 + n0 + bcol);
        float4 b1 = *(const float4*)(g_Wih_t + (size_t)(k0 + brow + 8) * G4 + n0 + bcol);
        __syncthreads();
        As[akq + 0][arow] = a0.x; As[akq + 1][arow] = a0.y;
        As[akq + 2][arow] = a0.z; As[akq + 3][arow] = a0.w;
        As[akq + 0][arow + 64] = a1.x; As[akq + 1][arow + 64] = a1.y;
        As[akq + 2][arow + 64] = a1.z; As[akq + 3][arow + 64] = a1.w;
        *(float4*)&Bs[brow][bcol]     = b0;
        *(float4*)&Bs[brow + 8][bcol] = b1;
        __syncthreads();
#pragma unroll
        for (int kk = 0; kk < 16; kk++) {
            float4 aA = *(float4*)&As[kk][ty * 8];
            float4 aB = *(float4*)&As[kk][ty * 8 + 4];
            float4 bA = *(float4*)&Bs[kk][tx * 8];
            float4 bB = *(float4*)&Bs[kk][tx * 8 + 4];
            ull bp0 = pack2(bA.x, bA.y);
            ull bp1 = pack2(bA.z, bA.w);
            ull bp2 = pack2(bB.x, bB.y);
            ull bp3 = pack2(bB.z, bB.w);
            float av[8] = {aA.x, aA.y, aA.z, aA.w, aB.x, aB.y, aB.z, aB.w};
#pragma unroll
            for (int i = 0; i < 8; i++) {
                ull ap = dup2(av[i]);
                fma2u(acc[i][0], ap, bp0);
                fma2u(acc[i][1], ap, bp1);
                fma2u(acc[i][2], ap, bp2);
                fma2u(acc[i][3], ap, bp3);
            }
        }
    }
#pragma unroll
    for (int i = 0; i < 8; i++) {
        int m = m0 + ty * 8 + i;
#pragma unroll
        for (int j = 0; j < 4; j++) {
            float2 v = unpack2(acc[i][j]);
            int c = n0 + tx * 8 + j * 2;
            v.x += g_bias[c];
            v.y += g_bias[c + 1];
            *(float2*)&g_xw[(size_t)m * G4 + c] = v;
        }
    }
}

// ---------------- persistent recurrence: all 128 timesteps in one kernel ---
// grid (32,4), 256 threads. CTA tile: 64 batch (n) x 64 gate-cols (16 units).
// Thread map: tn=tid&15 -> 4 n (A distinct per lane), tc=tid>>4 -> 1 hidden
// unit / 4 gate cols (B warp-broadcast). W_hh slice resident in SMEM (128KB).
// A staged in 32-k double buffers (16 syncs/step). c lives in registers.
// Cross-CTA sync: per-n-group barrier over 32 CTAs (4 independent groups).
__global__ __launch_bounds__(256, 1) void lstm_persist_kernel() {
    extern __shared__ float smem[];
    float* Ws = smem;                   // [512][64]  128KB
    float* Ab = smem + 512 * 64;        // 2 x [32][64]  16KB

    const int tid = threadIdx.x;
    const int c0  = blockIdx.x * 64;    // gate cols (permuted)
    const int gy  = blockIdx.y;         // n group
    const int n0  = gy * 64;            // batch base

    const int tn = tid & 15;            // n quad: rows n0+tn*4 .. +3
    const int tc = tid >> 4;            // col quad: cols c0+tc*4 .. +3 (1 unit)
    const int jh = (c0 >> 2) + tc;      // hidden unit owned by this thread
    const int nb = n0 + tn * 4;

    // staging map: 2 tasks/thread: (k=sk, nq) and (k=sk+16, nq)
    const int sk  = tid >> 4;           // 0..15
    const int snq = (tid & 15) * 4;

    // ---- load W_hh slice into SMEM once: Ws[k][cl] = g_Whh_t[k*G4 + c0+cl]
    for (int i = tid; i < 512 * 16; i += 256) {
        int k = i >> 4, cl = (i & 15) * 4;
        *(float4*)&Ws[k * 64 + cl] =
            *(const float4*)(g_Whh_t + (size_t)k * G4 + c0 + cl);
    }

    // c state in registers: c for (jh, nb..nb+3)
    float4 creg = *(const float4*)&g_cT[(size_t)jh * N_B + nb];
    __syncthreads();

    float* buf0 = Ab;
    float* buf1 = Ab + 32 * 64;

    for (int t = 0; t < T_S; t++) {
        const float* hin  = g_hT[t & 1];
        float*       hout = g_hT[(t + 1) & 1];

        // ---- prefetch epilogue operands (DRAM; consumed ~9us later)
        float4 xw0, xw1, xw2, xw3;
        {
            size_t base = ((size_t)nb * T_S + t) * G4 + c0 + tc * 4;
            const size_t rstride = (size_t)T_S * G4;
            xw0 = __ldcg((const float4*)(g_xw + base));
            xw1 = __ldcg((const float4*)(g_xw + base + rstride));
            xw2 = __ldcg((const float4*)(g_xw + base + 2 * rstride));
            xw3 = __ldcg((const float4*)(g_xw + base + 3 * rstride));
        }
        const float4 rr4 = *(const float4*)&g_rT[t * N_B + nb];
        const float4 r4s = *(const float4*)&g_rT[t * N_B + n0 + snq];

        // ---- stage k-block 0 (ld.cg: h ping-pong must bypass L1)
        {
            float4 h0 = __ldcg((const float4*)(hin + (size_t)sk        * N_B + n0 + snq));
            float4 h1 = __ldcg((const float4*)(hin + (size_t)(sk + 16) * N_B + n0 + snq));
            *(float4*)&buf0[sk        * 64 + snq] =
                make_float4(h0.x * r4s.x, h0.y * r4s.y, h0.z * r4s.z, h0.w * r4s.w);
            *(float4*)&buf0[(sk + 16) * 64 + snq] =
                make_float4(h1.x * r4s.x, h1.y * r4s.y, h1.z * r4s.z, h1.w * r4s.w);
        }
        __syncthreads();

        ull acc[4][2] = {};
        float* cur = buf0;
        float* nxt = buf1;

        for (int kb = 0; kb < 512; kb += 32) {
            float4 p0, p1;
            if (kb < 480) {
                p0 = __ldcg((const float4*)(hin + (size_t)(kb + 32 + sk)      * N_B + n0 + snq));
                p1 = __ldcg((const float4*)(hin + (size_t)(kb + 32 + sk + 16) * N_B + n0 + snq));
            }

            const float* Wk = Ws + kb * 64;
#pragma unroll
            for (int kk = 0; kk < 32; kk++) {
                float4 av = *(const float4*)(cur + kk * 64 + tn * 4);
                float4 bv = *(const float4*)(Wk + kk * 64 + tc * 4);
                ull bp0 = pack2(bv.x, bv.y);
                ull bp1 = pack2(bv.z, bv.w);
                float aa[4] = {av.x, av.y, av.z, av.w};
#pragma unroll
                for (int i = 0; i < 4; i++) {
                    ull ap = dup2(aa[i]);
                    fma2u(acc[i][0], ap, bp0);
                    fma2u(acc[i][1], ap, bp1);
                }
            }

            if (kb < 480) {
                *(float4*)&nxt[sk        * 64 + snq] =
                    make_float4(p0.x * r4s.x, p0.y * r4s.y, p0.z * r4s.z, p0.w * r4s.w);
                *(float4*)&nxt[(sk + 16) * 64 + snq] =
                    make_float4(p1.x * r4s.x, p1.y * r4s.y, p1.z * r4s.z, p1.w * r4s.w);
            }
            __syncthreads();
            float* tmp = cur; cur = nxt; nxt = tmp;
        }

        // ---- fused LSTM cell epilogue: 4 cells (4 n, 1 hidden unit)
        float hv[4];
        {
            const float4 xws[4] = {xw0, xw1, xw2, xw3};
            const float  rrs[4] = {rr4.x, rr4.y, rr4.z, rr4.w};
            float* cp = (float*)&creg;
#pragma unroll
            for (int i = 0; i < 4; i++) {
                float2 gif = unpack2(acc[i][0]);
                float2 ggo = unpack2(acc[i][1]);
                float gi = gif.x + xws[i].x;
                float gf = gif.y + xws[i].y;
                float gg = ggo.x + xws[i].z;
                float go = ggo.y + xws[i].w;
                float cn = sigf(gf) * (cp[i] * rrs[i]) + sigf(gi) * tanhf(gg);
                float hn = sigf(go) * tanhf(cn);
                cp[i] = cn;
                hv[i] = hn;
                g_hs[((size_t)(nb + i) * T_S + t) * H_D + jh] = hn;
            }
        }
        *(float4*)&hout[(size_t)jh * N_B + nb] = make_float4(hv[0], hv[1], hv[2], hv[3]);

        if (t == T_S - 1) {
#pragma unroll
            for (int i = 0; i < 4; i++) {
                g_hfin[(size_t)(nb + i) * H_D + jh] = hv[i];
                g_cfin[(size_t)(nb + i) * H_D + jh] = ((float*)&creg)[i];
            }
        }

        // ---- per-group grid barrier (32 CTAs sharing this n-slice)
        if (t < T_S - 1) {
            __syncthreads();
            if (tid == 0) {
                __threadfence();
                atomicAdd(&g_bar4[gy], 1u);
                unsigned target = 32u * (unsigned)(t + 1);
                while (*(volatile unsigned*)&g_bar4[gy] < target) { }
                __threadfence();
            }
            __syncthreads();
        }
    }
}

// ---------------- output GEMM: out = mish(hs @ Wout_t + b_out) -------------
__global__ __launch_bounds__(256) void gemm_out_kernel(const float* __restrict__ b_out,
                                                       float* __restrict__ out) {
    __shared__ float As[16][128];
    __shared__ float Bs[16][128];
    int tid = threadIdx.x;
    int m0 = blockIdx.y * 128;
    int n0 = blockIdx.x * 128;
    int ty = tid >> 4, tx = tid & 15;

    int arow = tid >> 2;
    int akq  = (tid & 3) * 4;
    int brow = tid >> 5;
    int bcol = (tid & 31) * 4;

    ull acc[8][4] = {};

    for (int k0 = 0; k0 < H_D; k0 += 16) {
        float4 a0 = *(const float4*)(g_hs + (size_t)(m0 + arow)      * H_D + k0 + akq);
        float4 a1 = *(const float4*)(g_hs + (size_t)(m0 + arow + 64) * H_D + k0 + akq);
        float4 b0 = *(const float4*)(g_Wout_t + (size_t)(k0 + brow)     * H_D + n0 + bcol);
        float4 b1 = *(const float4*)(g_Wout_t + (size_t)(k0 + brow + 8) * H_D + n0 + bcol);
        __syncthreads();
        As[akq + 0][arow] = a0.x; As[akq + 1][arow] = a0.y;
        As[akq + 2][arow] = a0.z; As[akq + 3][arow] = a0.w;
        As[akq + 0][arow + 64] = a1.x; As[akq + 1][arow + 64] = a1.y;
        As[akq + 2][arow + 64] = a1.z; As[akq + 3][arow + 64] = a1.w;
        *(float4*)&Bs[brow][bcol]     = b0;
        *(float4*)&Bs[brow + 8][bcol] = b1;
        __syncthreads();
#pragma unroll
        for (int kk = 0; kk < 16; kk++) {
            float4 aA = *(float4*)&As[kk][ty * 8];
            float4 aB = *(float4*)&As[kk][ty * 8 + 4];
            float4 bA = *(float4*)&Bs[kk][tx * 8];
            float4 bB = *(float4*)&Bs[kk][tx * 8 + 4];
            ull bp0 = pack2(bA.x, bA.y);
            ull bp1 = pack2(bA.z, bA.w);
            ull bp2 = pack2(bB.x, bB.y);
            ull bp3 = pack2(bB.z, bB.w);
            float av[8] = {aA.x, aA.y, aA.z, aA.w, aB.x, aB.y, aB.z, aB.w};
#pragma unroll
            for (int i = 0; i < 8; i++) {
                ull ap = dup2(av[i]);
                fma2u(acc[i][0], ap, bp0);
                fma2u(acc[i][1], ap, bp1);
                fma2u(acc[i][2], ap, bp2);
                fma2u(acc[i][3], ap, bp3);
            }
        }
    }
#pragma unroll
    for (int i = 0; i < 8; i++) {
        int m = m0 + ty * 8 + i;
#pragma unroll
        for (int j = 0; j < 4; j++) {
            float2 v = unpack2(acc[i][j]);
            int c = n0 + tx * 8 + j * 2;
            float v0 = v.x + b_out[c];
            float v1 = v.y + b_out[c + 1];
            // mish(x) = x * tanh(log1p(exp(x)))
            float o0 = v0 * tanhf(log1pf(expf(v0)));
            float o1 = v1 * tanhf(log1pf(expf(v1)));
            out[(size_t)m * H_D + c]     = o0;
            out[(size_t)m * H_D + c + 1] = o1;
        }
    }
}

// ---------------- broadcast hT, cT to [N,T,H] -------------------------------
__global__ void bcast_kernel(float* __restrict__ out) {
    int i = blockIdx.x * blockDim.x + threadIdx.x;   // over NT*H_D/4 float4s
    if (i < NT * H_D / 4) {
        int row = i >> 7;      // H_D/4 = 128 float4 per row; row = n*T+t
        int f4  = i & 127;
        int n   = row >> 7;    // T = 128
        float4 hv = *(const float4*)&g_hfin[(size_t)n * H_D + f4 * 4];
        float4 cv = *(const float4*)&g_cfin[(size_t)n * H_D + f4 * 4];
        float4* o = (float4*)out;
        o[(size_t)(NT * H_D / 4) + i]     = hv;
        o[(size_t)(NT * H_D / 4) * 2 + i] = cv;
    }
}

// ---------------- launch ----------------------------------------------------
extern "C" void kernel_launch(void* const* d_in, const int* in_sizes, int n_in,
                              void* d_out, int out_size) {
    const float* x      = (const float*)d_in[0];
    const int*   isinit = (const int*)  d_in[1];
    const float* hx     = (const float*)d_in[2];
    const float* cx     = (const float*)d_in[3];
    const float* W_ih   = (const float*)d_in[4];
    const float* W_hh   = (const float*)d_in[5];
    const float* b_ih   = (const float*)d_in[6];
    const float* b_hh   = (const float*)d_in[7];
    const float* W_out  = (const float*)d_in[8];
    const float* b_out  = (const float*)d_in[9];
    float* out = (float*)d_out;

    const int SMEM_BYTES = (512 * 64 + 2 * 32 * 64) * (int)sizeof(float);  // 147456
    cudaFuncSetAttribute(lstm_persist_kernel,
                         cudaFuncAttributeMaxDynamicSharedMemorySize, SMEM_BYTES);

    prep_kernel<<<(I_D * G4 + 255) / 256, 256>>>(W_ih, W_hh, b_ih, b_hh, W_out);
    init_kernel<<<(N_B * H_D + 255) / 256, 256>>>(hx, cx, isinit);

    { dim3 g(G4 / 128, NT / 128); gemm_xw_kernel<<<g, 256>>>(x); }

    { dim3 g(32, 4); lstm_persist_kernel<<<g, 256, SMEM_BYTES>>>(); }

    { dim3 g(H_D / 128, NT / 128); gemm_out_kernel<<<g, 256>>>(b_out, out); }

    bcast_kernel<<<(NT * H_D / 4 + 255) / 256, 256>>>(out);
}